// round 6
// baseline (speedup 1.0000x reference)
#include <cuda_runtime.h>
#include <math.h>

#define N_NODES 100000
#define N_EDGES 1000000
#define F 32
#define DFEAT 160            // 5 segments x 32
#define BM 128               // GEMM M tile

typedef unsigned long long u64;

// ---------------- scratch (device globals; no allocation) ----------------
__device__ __align__(16) float g_deg[2 * N_NODES];        // [deg_out | deg_in]
__device__ __align__(16) float g_norm[2 * N_EDGES];       // [norm_out | norm_in]
__device__ __align__(16) float g_T1o[N_NODES * F];
__device__ __align__(16) float g_T1i[N_NODES * F];
__device__ __align__(16) float g_P2o[N_NODES * F];
__device__ __align__(16) float g_P2i[N_NODES * F];
__device__ __align__(16) float g_W[DFEAT * 64];           // [f][64]: cols 0-31 Wz_eff, 32-63 Wh_eff

// ---------------- helpers ----------------
__device__ __forceinline__ void red4(float* p, float a, float b, float c, float d) {
    asm volatile("red.global.add.v4.f32 [%0], {%1,%2,%3,%4};"
                 :: "l"(p), "f"(a), "f"(b), "f"(c), "f"(d) : "memory");
}
__device__ __forceinline__ u64 ffma2(u64 a, u64 b, u64 c) {
    u64 d; asm("fma.rn.f32x2 %0, %1, %2, %3;" : "=l"(d) : "l"(a), "l"(b), "l"(c)); return d;
}
__device__ __forceinline__ float2 unpack2(u64 v) {
    float2 f; asm("mov.b64 {%0,%1}, %2;" : "=f"(f.x), "=f"(f.y) : "l"(v)); return f;
}

// ---------------- kernels ----------------
__global__ void deg_kernel(const int* __restrict__ src, const int* __restrict__ dst,
                           const float* __restrict__ ew) {
    int e = blockIdx.x * blockDim.x + threadIdx.x;
    if (e >= N_EDGES) return;
    float w = ew[e];
    atomicAdd(&g_deg[src[e]], w);
    atomicAdd(&g_deg[N_NODES + dst[e]], w);
}

__global__ void norm_kernel(const int* __restrict__ src, const int* __restrict__ dst,
                            const float* __restrict__ ew) {
    int e = blockIdx.x * blockDim.x + threadIdx.x;
    if (e >= N_EDGES) return;
    float w = ew[e];
    g_norm[e]           = w / g_deg[src[e]];
    g_norm[N_EDGES + e] = w / g_deg[N_NODES + dst[e]];
}

// hop 1: T1o[dst] += norm_out * X[src]; T1i[src] += norm_in * X[dst]
__global__ void prop1_kernel(const float* __restrict__ X,
                             const int* __restrict__ src, const int* __restrict__ dst) {
    long idx = (long)blockIdx.x * blockDim.x + threadIdx.x;
    int e = (int)(idx >> 3);
    if (e >= N_EDGES) return;
    int q = (int)(idx & 7);
    int s = src[e], d = dst[e];
    float no = g_norm[e], ni = g_norm[N_EDGES + e];
    float4 a = ((const float4*)X)[s * 8 + q];
    red4(&g_T1o[d * F + q * 4], a.x * no, a.y * no, a.z * no, a.w * no);
    float4 b = ((const float4*)X)[d * 8 + q];
    red4(&g_T1i[s * F + q * 4], b.x * ni, b.y * ni, b.z * ni, b.w * ni);
}

// hop 2: P2o[dst] += norm_out * T1o[src]; P2i[src] += norm_in * T1i[dst]
__global__ void prop2_kernel(const int* __restrict__ src, const int* __restrict__ dst) {
    long idx = (long)blockIdx.x * blockDim.x + threadIdx.x;
    int e = (int)(idx >> 3);
    if (e >= N_EDGES) return;
    int q = (int)(idx & 7);
    int s = src[e], d = dst[e];
    float no = g_norm[e], ni = g_norm[N_EDGES + e];
    float4 a = ((const float4*)g_T1o)[s * 8 + q];
    red4(&g_P2o[d * F + q * 4], a.x * no, a.y * no, a.z * no, a.w * no);
    float4 b = ((const float4*)g_T1i)[d * 8 + q];
    red4(&g_P2i[s * F + q * 4], b.x * ni, b.y * ni, b.z * ni, b.w * ni);
}

// Build W_eff[160][64].  W layout: [2][3][64][32], only rows <32 matter (H-half is zero).
__global__ void wprep_kernel(const float* __restrict__ Wz, const float* __restrict__ Wh) {
    int idx = blockIdx.x * blockDim.x + threadIdx.x;
    if (idx >= 2 * DFEAT * F) return;
    int gate = idx / (DFEAT * F);
    int rem  = idx % (DFEAT * F);
    int f = rem / F, j = rem % F;
    int seg = f >> 5, r = f & 31;
    const float* W = gate ? Wh : Wz;
    float v;
    if (seg == 0)      v = W[(0 * 64 + r) * 32 + j] + W[(3 * 64 + r) * 32 + j]
                         - W[(2 * 64 + r) * 32 + j] - W[(5 * 64 + r) * 32 + j];
    else if (seg == 1) v = W[(1 * 64 + r) * 32 + j];
    else if (seg == 2) v = W[(4 * 64 + r) * 32 + j];
    else if (seg == 3) v = 2.f * W[(2 * 64 + r) * 32 + j];
    else               v = 2.f * W[(5 * 64 + r) * 32 + j];
    g_W[f * 64 + gate * 32 + j] = v;
}

// Fused GEMM [BM x 160] @ [160 x 64] + GRU epilogue.
// Inner loop: pure LDS.128 + FFMA2 — packed operands come directly from smem:
//   A pairs from transposed As rows; B (b,b) pairs from a pre-duplicated BsDup tile.
// 128 threads: ty=tid>>3 (16 groups, 8 M-rows each), tx=tid&7 (cols {4tx..4tx+3} of both halves).
__global__ __launch_bounds__(128) void gemm_kernel(
    const float* __restrict__ X,
    const float* __restrict__ bz, const float* __restrict__ bh,
    const float* __restrict__ wl, const float* __restrict__ bl,
    float* __restrict__ out)
{
    __shared__ __align__(16) float As[32][BM + 4];     // stride 132 floats (528B, 16B-aligned rows)
    __shared__ __align__(16) float BsDup[32][128];     // col j duplicated at [2j],[2j+1]

    int tid = threadIdx.x;
    int tx = tid & 7;
    int ty = tid >> 3;
    int m0 = ty * 8;
    int blockm = blockIdx.x * BM;

    // acc2[mp][j]: m-pair (2mp,2mp+1); j<4 -> z cols tx*4+j, j>=4 -> h cols 32+tx*4+(j-4)
    u64 acc2[4][8];
#pragma unroll
    for (int i = 0; i < 4; i++)
#pragma unroll
        for (int j = 0; j < 8; j++) acc2[i][j] = 0ull;

    const float* segp[5] = { X, g_T1o, g_T1i, g_P2o, g_P2i };

    for (int ks = 0; ks < 5; ks++) {
        const float* A = segp[ks];
        // A tile: 128 nodes x 32 feats, stored transposed As[kk][m]
#pragma unroll
        for (int i = 0; i < 8; i++) {
            int idx = i * 128 + tid;          // 0..1023
            int m  = idx >> 3;
            int f4 = idx & 7;
            int node = blockm + m;
            float4 v = (node < N_NODES) ? ((const float4*)A)[node * 8 + f4]
                                        : make_float4(0.f, 0.f, 0.f, 0.f);
            As[f4 * 4 + 0][m] = v.x;
            As[f4 * 4 + 1][m] = v.y;
            As[f4 * 4 + 2][m] = v.z;
            As[f4 * 4 + 3][m] = v.w;
        }
        // B tile duplicated: BsDup[kk][2j],[2j+1] = Wrow[j]
#pragma unroll
        for (int i = 0; i < 4; i++) {
            int fidx = i * 128 + tid;         // float4 idx into 32x64 tile, 0..511
            float4 v = ((const float4*)g_W)[ks * 512 + fidx];
            int r  = fidx >> 4;               // kk row (16 float4 per 64-col row)
            int c  = (fidx & 15) * 4;         // base col
            float2* drow = (float2*)&BsDup[r][0];
            drow[c + 0] = make_float2(v.x, v.x);
            drow[c + 1] = make_float2(v.y, v.y);
            drow[c + 2] = make_float2(v.z, v.z);
            drow[c + 3] = make_float2(v.w, v.w);
        }
        __syncthreads();

#pragma unroll 4
        for (int kk = 0; kk < 32; kk++) {
            // A: 8 m-values as 4 packed pairs, straight from two LDS.128
            u64 a01_23[2], a45_67[2];
            *(float4*)a01_23 = *(const float4*)&As[kk][m0];
            *(float4*)a45_67 = *(const float4*)&As[kk][m0 + 4];
            u64 aa[4] = { a01_23[0], a01_23[1], a45_67[0], a45_67[1] };
            // B: 8 duplicated (b,b) pairs from four LDS.128
            u64 bz01[2], bz23[2], bh01[2], bh23[2];
            *(float4*)bz01 = *(const float4*)&BsDup[kk][tx * 8];
            *(float4*)bz23 = *(const float4*)&BsDup[kk][tx * 8 + 4];
            *(float4*)bh01 = *(const float4*)&BsDup[kk][64 + tx * 8];
            *(float4*)bh23 = *(const float4*)&BsDup[kk][64 + tx * 8 + 4];
            u64 bb[8] = { bz01[0], bz01[1], bz23[0], bz23[1],
                          bh01[0], bh01[1], bh23[0], bh23[1] };
#pragma unroll
            for (int mp = 0; mp < 4; mp++)
#pragma unroll
                for (int j = 0; j < 8; j++)
                    acc2[mp][j] = ffma2(aa[mp], bb[j], acc2[mp][j]);
        }
        __syncthreads();
    }

    // epilogue: z = sigmoid(gz), ht = tanh(gh), H = (1-z)*ht, y = relu(H) . wl + bl
    float bzv[4], bhv[4], wlv[4];
#pragma unroll
    for (int jj = 0; jj < 4; jj++) {
        int j = tx * 4 + jj;
        bzv[jj] = bz[j];
        bhv[jj] = bh[j];
        wlv[jj] = wl[j];
    }
    float bl0 = bl[0];

#pragma unroll
    for (int i = 0; i < 8; i++) {
        int mp = i >> 1, hi = i & 1;
        float gzv[4], ghv[4];
#pragma unroll
        for (int jj = 0; jj < 4; jj++) {
            float2 z2 = unpack2(acc2[mp][jj]);
            float2 h2 = unpack2(acc2[mp][jj + 4]);
            gzv[jj] = hi ? z2.y : z2.x;
            ghv[jj] = hi ? h2.y : h2.x;
        }
        float y = 0.f;
#pragma unroll
        for (int jj = 0; jj < 4; jj++) {
            float gz = gzv[jj] + bzv[jj];
            float gh = ghv[jj] + bhv[jj];
            float z  = 1.f / (1.f + expf(-gz));
            float ht = tanhf(gh);
            float Hv = (1.f - z) * ht;
            y += fmaxf(Hv, 0.f) * wlv[jj];
        }
        y += __shfl_xor_sync(0xffffffffu, y, 4);
        y += __shfl_xor_sync(0xffffffffu, y, 2);
        y += __shfl_xor_sync(0xffffffffu, y, 1);
        if (tx == 0) {
            int node = blockm + m0 + i;
            if (node < N_NODES) out[node] = y + bl0;
        }
    }
}

// ---------------- launch ----------------
extern "C" void kernel_launch(void* const* d_in, const int* in_sizes, int n_in,
                              void* d_out, int out_size) {
    const float* x  = (const float*)d_in[0];
    const int*   ei = (const int*)d_in[1];
    const float* ew = (const float*)d_in[2];
    const float* Wz = (const float*)d_in[5];
    const float* bz = (const float*)d_in[6];
    const float* Wh = (const float*)d_in[9];
    const float* bh = (const float*)d_in[10];
    const float* Wl = (const float*)d_in[11];
    const float* bl = (const float*)d_in[12];
    float* out = (float*)d_out;

    const int* src = ei;
    const int* dst = ei + N_EDGES;

    void *p_deg, *p_t1o, *p_t1i, *p_p2o, *p_p2i;
    cudaGetSymbolAddress(&p_deg, g_deg);
    cudaGetSymbolAddress(&p_t1o, g_T1o);
    cudaGetSymbolAddress(&p_t1i, g_T1i);
    cudaGetSymbolAddress(&p_p2o, g_P2o);
    cudaGetSymbolAddress(&p_p2i, g_P2i);

    cudaMemsetAsync(p_deg, 0, 2 * N_NODES * sizeof(float), 0);
    cudaMemsetAsync(p_t1o, 0, N_NODES * F * sizeof(float), 0);
    cudaMemsetAsync(p_t1i, 0, N_NODES * F * sizeof(float), 0);
    cudaMemsetAsync(p_p2o, 0, N_NODES * F * sizeof(float), 0);
    cudaMemsetAsync(p_p2i, 0, N_NODES * F * sizeof(float), 0);

    deg_kernel<<<(N_EDGES + 255) / 256, 256>>>(src, dst, ew);
    norm_kernel<<<(N_EDGES + 255) / 256, 256>>>(src, dst, ew);
    prop1_kernel<<<(N_EDGES * 8 + 255) / 256, 256>>>(x, src, dst);
    prop2_kernel<<<(N_EDGES * 8 + 255) / 256, 256>>>(src, dst);
    wprep_kernel<<<(2 * DFEAT * F + 255) / 256, 256>>>(Wz, Wh);
    gemm_kernel<<<(N_NODES + BM - 1) / BM, 128>>>(x, bz, bh, Wl, bl, out);
}

// round 7
// speedup vs baseline: 1.3620x; 1.3620x over previous
#include <cuda_runtime.h>
#include <math.h>

#define N_NODES 100000
#define N_EDGES 1000000
#define F 32
#define DFEAT 160            // 5 segments x 32
#define BM 128               // GEMM M tile

// ---------------- scratch (device globals; no allocation) ----------------
__device__ __align__(16) float g_deg[2 * N_NODES];        // [deg_out | deg_in]
__device__ __align__(16) float g_norm[2 * N_EDGES];       // [norm_out | norm_in]
__device__ __align__(16) float g_T1o[N_NODES * F];
__device__ __align__(16) float g_T1i[N_NODES * F];
__device__ __align__(16) float g_P2o[N_NODES * F];
__device__ __align__(16) float g_P2i[N_NODES * F];
__device__ __align__(16) float g_W[DFEAT * 64];           // [f][64]: cols 0-31 Wz_eff, 32-63 Wh_eff

// ---------------- helpers ----------------
__device__ __forceinline__ void red4(float* p, float a, float b, float c, float d) {
    asm volatile("red.global.add.v4.f32 [%0], {%1,%2,%3,%4};"
                 :: "l"(p), "f"(a), "f"(b), "f"(c), "f"(d) : "memory");
}
__device__ __forceinline__ float tf32r(float x) {   // round f32 -> tf32 (rna), keep as float
    unsigned u;
    asm("cvt.rna.tf32.f32 %0, %1;" : "=r"(u) : "f"(x));
    return __uint_as_float(u);
}
__device__ __forceinline__ void mma_tf32(float c[4], unsigned a0, unsigned a1, unsigned a2,
                                         unsigned a3, unsigned b0, unsigned b1) {
    asm("mma.sync.aligned.m16n8k8.row.col.f32.tf32.tf32.f32 "
        "{%0,%1,%2,%3}, {%4,%5,%6,%7}, {%8,%9}, {%0,%1,%2,%3};"
        : "+f"(c[0]), "+f"(c[1]), "+f"(c[2]), "+f"(c[3])
        : "r"(a0), "r"(a1), "r"(a2), "r"(a3), "r"(b0), "r"(b1));
}

// ---------------- kernels ----------------
__global__ void deg_kernel(const int* __restrict__ src, const int* __restrict__ dst,
                           const float* __restrict__ ew) {
    int e = blockIdx.x * blockDim.x + threadIdx.x;
    if (e >= N_EDGES) return;
    float w = ew[e];
    atomicAdd(&g_deg[src[e]], w);
    atomicAdd(&g_deg[N_NODES + dst[e]], w);
}

__global__ void norm_kernel(const int* __restrict__ src, const int* __restrict__ dst,
                            const float* __restrict__ ew) {
    int e = blockIdx.x * blockDim.x + threadIdx.x;
    if (e >= N_EDGES) return;
    float w = ew[e];
    g_norm[e]           = w / g_deg[src[e]];
    g_norm[N_EDGES + e] = w / g_deg[N_NODES + dst[e]];
}

// hop 1: T1o[dst] += norm_out * X[src]; T1i[src] += norm_in * X[dst]
__global__ void prop1_kernel(const float* __restrict__ X,
                             const int* __restrict__ src, const int* __restrict__ dst) {
    long idx = (long)blockIdx.x * blockDim.x + threadIdx.x;
    int e = (int)(idx >> 3);
    if (e >= N_EDGES) return;
    int q = (int)(idx & 7);
    int s = src[e], d = dst[e];
    float no = g_norm[e], ni = g_norm[N_EDGES + e];
    float4 a = ((const float4*)X)[s * 8 + q];
    red4(&g_T1o[d * F + q * 4], a.x * no, a.y * no, a.z * no, a.w * no);
    float4 b = ((const float4*)X)[d * 8 + q];
    red4(&g_T1i[s * F + q * 4], b.x * ni, b.y * ni, b.z * ni, b.w * ni);
}

// hop 2: P2o[dst] += norm_out * T1o[src]; P2i[src] += norm_in * T1i[dst]
__global__ void prop2_kernel(const int* __restrict__ src, const int* __restrict__ dst) {
    long idx = (long)blockIdx.x * blockDim.x + threadIdx.x;
    int e = (int)(idx >> 3);
    if (e >= N_EDGES) return;
    int q = (int)(idx & 7);
    int s = src[e], d = dst[e];
    float no = g_norm[e], ni = g_norm[N_EDGES + e];
    float4 a = ((const float4*)g_T1o)[s * 8 + q];
    red4(&g_P2o[d * F + q * 4], a.x * no, a.y * no, a.z * no, a.w * no);
    float4 b = ((const float4*)g_T1i)[d * 8 + q];
    red4(&g_P2i[s * F + q * 4], b.x * ni, b.y * ni, b.z * ni, b.w * ni);
}

// Build W_eff[160][64].  W layout: [2][3][64][32], only rows <32 matter (H-half is zero).
__global__ void wprep_kernel(const float* __restrict__ Wz, const float* __restrict__ Wh) {
    int idx = blockIdx.x * blockDim.x + threadIdx.x;
    if (idx >= 2 * DFEAT * F) return;
    int gate = idx / (DFEAT * F);
    int rem  = idx % (DFEAT * F);
    int f = rem / F, j = rem % F;
    int seg = f >> 5, r = f & 31;
    const float* W = gate ? Wh : Wz;
    float v;
    if (seg == 0)      v = W[(0 * 64 + r) * 32 + j] + W[(3 * 64 + r) * 32 + j]
                         - W[(2 * 64 + r) * 32 + j] - W[(5 * 64 + r) * 32 + j];
    else if (seg == 1) v = W[(1 * 64 + r) * 32 + j];
    else if (seg == 2) v = W[(4 * 64 + r) * 32 + j];
    else if (seg == 3) v = 2.f * W[(2 * 64 + r) * 32 + j];
    else               v = 2.f * W[(5 * 64 + r) * 32 + j];
    g_W[f * 64 + gate * 32 + j] = v;
}

// ---------------- tensor-core GEMM + fused GRU epilogue ----------------
// [BM x 160] @ [160 x 64] via mma.sync.m16n8k8.tf32, fp32 accumulate.
// 128 threads = 4 warps; warp w owns rows w*32..w*32+31 (2 m-frags), all 64 cols (8 n-frags).
// A smem stride 36 -> frag-load banks (4g+tg) all distinct; B stride 72 -> (8tg+g) all distinct.
__global__ __launch_bounds__(128) void gemm_kernel(
    const float* __restrict__ X,
    const float* __restrict__ bz, const float* __restrict__ bh,
    const float* __restrict__ wl, const float* __restrict__ bl,
    float* __restrict__ out)
{
    __shared__ __align__(16) float As[BM][36];   // [m][k], tf32-rounded
    __shared__ __align__(16) float Bs[32][72];   // [k][n], tf32-rounded

    int tid  = threadIdx.x;
    int w    = tid >> 5;
    int lane = tid & 31;
    int g    = lane >> 2;      // 0..7
    int tg   = lane & 3;       // 0..3
    int blockm = blockIdx.x * BM;

    float c[2][8][4];
#pragma unroll
    for (int mf = 0; mf < 2; mf++)
#pragma unroll
        for (int n = 0; n < 8; n++)
#pragma unroll
            for (int k = 0; k < 4; k++) c[mf][n][k] = 0.f;

    const float* segp[5] = { X, g_T1o, g_T1i, g_P2o, g_P2i };

    for (int ks = 0; ks < 5; ks++) {
        const float* A = segp[ks];
        // A tile: 128 nodes x 32 feats, row-major, tf32-rounded
#pragma unroll
        for (int i = 0; i < 8; i++) {
            int idx = i * 128 + tid;          // 0..1023
            int m  = idx >> 3;
            int f4 = idx & 7;
            int node = blockm + m;
            float4 v = (node < N_NODES) ? ((const float4*)A)[node * 8 + f4]
                                        : make_float4(0.f, 0.f, 0.f, 0.f);
            float4 t = make_float4(tf32r(v.x), tf32r(v.y), tf32r(v.z), tf32r(v.w));
            *(float4*)&As[m][f4 * 4] = t;     // 144B row stride: 16B-aligned
        }
        // B tile: 32 x 64, tf32-rounded
#pragma unroll
        for (int i = 0; i < 4; i++) {
            int fidx = i * 128 + tid;         // float4 idx, 0..511
            float4 v = ((const float4*)g_W)[ks * 512 + fidx];
            int r  = fidx >> 4;
            int c4 = (fidx & 15) * 4;
            float4 t = make_float4(tf32r(v.x), tf32r(v.y), tf32r(v.z), tf32r(v.w));
            *(float4*)&Bs[r][c4] = t;         // 288B row stride: 16B-aligned
        }
        __syncthreads();

#pragma unroll
        for (int kst = 0; kst < 4; kst++) {
            int kb = kst * 8;
            unsigned a[2][4];
#pragma unroll
            for (int mf = 0; mf < 2; mf++) {
                int mb = w * 32 + mf * 16;
                a[mf][0] = __float_as_uint(As[mb + g    ][kb + tg    ]);
                a[mf][1] = __float_as_uint(As[mb + g + 8][kb + tg    ]);
                a[mf][2] = __float_as_uint(As[mb + g    ][kb + tg + 4]);
                a[mf][3] = __float_as_uint(As[mb + g + 8][kb + tg + 4]);
            }
#pragma unroll
            for (int n = 0; n < 8; n++) {
                unsigned b0 = __float_as_uint(Bs[kb + tg    ][n * 8 + g]);
                unsigned b1 = __float_as_uint(Bs[kb + tg + 4][n * 8 + g]);
                mma_tf32(c[0][n], a[0][0], a[0][1], a[0][2], a[0][3], b0, b1);
                mma_tf32(c[1][n], a[1][0], a[1][1], a[1][2], a[1][3], b0, b1);
            }
        }
        __syncthreads();
    }

    // epilogue. Thread holds, per n-frag n and cc in {0,1}: col = n*8 + 2*tg + cc,
    // rows g (c[..][0..1]) and g+8 (c[..][2..3]). n<4 are z-gates; n+4 the matching h-gates.
    float bzv[4][2], bhv[4][2], wlv[4][2];
#pragma unroll
    for (int n = 0; n < 4; n++)
#pragma unroll
        for (int cc = 0; cc < 2; cc++) {
            int col = n * 8 + 2 * tg + cc;
            bzv[n][cc] = bz[col];
            bhv[n][cc] = bh[col];
            wlv[n][cc] = wl[col];
        }
    float bl0 = bl[0];

#pragma unroll
    for (int mf = 0; mf < 2; mf++) {
#pragma unroll
        for (int rh = 0; rh < 2; rh++) {
            float y = 0.f;
#pragma unroll
            for (int n = 0; n < 4; n++) {
#pragma unroll
                for (int cc = 0; cc < 2; cc++) {
                    float gz = c[mf][n    ][rh * 2 + cc] + bzv[n][cc];
                    float gh = c[mf][n + 4][rh * 2 + cc] + bhv[n][cc];
                    float z  = 1.f / (1.f + expf(-gz));
                    float ht = tanhf(gh);
                    float Hv = (1.f - z) * ht;
                    y += fmaxf(Hv, 0.f) * wlv[n][cc];
                }
            }
            // reduce over tg quad (lanes 4g+0..4g+3)
            y += __shfl_xor_sync(0xffffffffu, y, 1);
            y += __shfl_xor_sync(0xffffffffu, y, 2);
            if (tg == 0) {
                int node = blockm + w * 32 + mf * 16 + rh * 8 + g;
                if (node < N_NODES) out[node] = y + bl0;
            }
        }
    }
}

// ---------------- launch ----------------
extern "C" void kernel_launch(void* const* d_in, const int* in_sizes, int n_in,
                              void* d_out, int out_size) {
    const float* x  = (const float*)d_in[0];
    const int*   ei = (const int*)d_in[1];
    const float* ew = (const float*)d_in[2];
    const float* Wz = (const float*)d_in[5];
    const float* bz = (const float*)d_in[6];
    const float* Wh = (const float*)d_in[9];
    const float* bh = (const float*)d_in[10];
    const float* Wl = (const float*)d_in[11];
    const float* bl = (const float*)d_in[12];
    float* out = (float*)d_out;

    const int* src = ei;
    const int* dst = ei + N_EDGES;

    void *p_deg, *p_t1o, *p_t1i, *p_p2o, *p_p2i;
    cudaGetSymbolAddress(&p_deg, g_deg);
    cudaGetSymbolAddress(&p_t1o, g_T1o);
    cudaGetSymbolAddress(&p_t1i, g_T1i);
    cudaGetSymbolAddress(&p_p2o, g_P2o);
    cudaGetSymbolAddress(&p_p2i, g_P2i);

    cudaMemsetAsync(p_deg, 0, 2 * N_NODES * sizeof(float), 0);
    cudaMemsetAsync(p_t1o, 0, N_NODES * F * sizeof(float), 0);
    cudaMemsetAsync(p_t1i, 0, N_NODES * F * sizeof(float), 0);
    cudaMemsetAsync(p_p2o, 0, N_NODES * F * sizeof(float), 0);
    cudaMemsetAsync(p_p2i, 0, N_NODES * F * sizeof(float), 0);

    deg_kernel<<<(N_EDGES + 255) / 256, 256>>>(src, dst, ew);
    norm_kernel<<<(N_EDGES + 255) / 256, 256>>>(src, dst, ew);
    prop1_kernel<<<(N_EDGES * 8 + 255) / 256, 256>>>(x, src, dst);
    prop2_kernel<<<(N_EDGES * 8 + 255) / 256, 256>>>(src, dst);
    wprep_kernel<<<(2 * DFEAT * F + 255) / 256, 256>>>(Wz, Wh);
    gemm_kernel<<<(N_NODES + BM - 1) / BM, 128>>>(x, bz, bh, Wl, bl, out);
}